// round 14
// baseline (speedup 1.0000x reference)
#include <cuda_runtime.h>
#include <cuda_fp16.h>
#include <cstdint>

// ---------------------------------------------------------------------------
// GAT layer. Graph-parallel pipeline:
//   NULL stream:  count(+detect,+zero tilestat) -> lookback-scan(+selfloop)
//                 -> scatter(+detect)                                  ┐
//   side stream:  GEMM h=xW (HMMA tensor cores)                       ├→ aggregate
// ---------------------------------------------------------------------------

#define MAXN 100000
#define MAXE 1600000
#define SCAN_T 512
#define ASTRIDE 136   // 128 halfs + 8 pad -> 272B row stride (4-bank shift/row)

__device__ __half g_h16[(size_t)MAXN * 128];
__device__ float g_asrc[MAXN];
__device__ float g_adst[MAXN];
__device__ int   g_counts[MAXN];
__device__ int   g_offsets[MAXN + 1];
__device__ int   g_cursor[MAXN];
__device__ int   g_csr[MAXN + MAXE];
__device__ unsigned long long g_tilestat[256];   // lookback status; re-zeroed by count each call
__device__ unsigned g_amax = 0x00800000u;        // enc_f(-FLT_MAX); monotone, replay-idempotent

__device__ __forceinline__ unsigned h2_as_u32(__half2 h) {
    union { __half2 h; unsigned u; } c; c.h = h; return c.u;
}
__device__ __forceinline__ __half2 u32_as_h2(unsigned u) {
    union { unsigned u; __half2 h; } c; c.u = u; return c.h;
}
__device__ __forceinline__ unsigned enc_f(float f) {
    unsigned u = __float_as_uint(f);
    return (u & 0x80000000u) ? ~u : (u | 0x80000000u);
}
__device__ __forceinline__ float dec_f(unsigned e) {
    return (e & 0x80000000u) ? __uint_as_float(e ^ 0x80000000u)
                             : __uint_as_float(~e);
}
__device__ __forceinline__ uint32_t smem_u32(const void* p) {
    return (uint32_t)__cvta_generic_to_shared(p);
}
__device__ __forceinline__ void ldsm_x4(uint32_t* r, uint32_t addr) {
    asm volatile("ldmatrix.sync.aligned.m8n8.x4.shared.b16 {%0,%1,%2,%3}, [%4];"
                 : "=r"(r[0]), "=r"(r[1]), "=r"(r[2]), "=r"(r[3]) : "r"(addr));
}
__device__ __forceinline__ void mma16816(float* d, const uint32_t* a,
                                         uint32_t b0, uint32_t b1) {
    asm volatile(
        "mma.sync.aligned.m16n8k16.row.col.f32.f16.f16.f32 "
        "{%0,%1,%2,%3}, {%4,%5,%6,%7}, {%8,%9}, {%0,%1,%2,%3};"
        : "+f"(d[0]), "+f"(d[1]), "+f"(d[2]), "+f"(d[3])
        : "r"(a[0]), "r"(a[1]), "r"(a[2]), "r"(a[3]), "r"(b0), "r"(b1));
}

// inline per-block dtype detection: sample first 256 odd 32-bit words.
// int64 => high halves, all zero. int32 => src node ids (P(all 0) ~ 0).
__device__ __forceinline__ bool detect_is64_block(const void* edges, int E) {
    const unsigned* w = (const unsigned*)edges;
    int samp = threadIdx.x & 255;
    int nz = (samp < E) ? (w[2 * (size_t)samp + 1] != 0u) : 0;
    return __syncthreads_or(nz) == 0;
}

// ---------------------------------------------------------------------------
// 1. histogram (+ tilestat zeroing + inline detection)
// ---------------------------------------------------------------------------
__global__ void count_edges_kernel(const void* __restrict__ edges, int E) {
    bool is64 = detect_is64_block(edges, E);
    int tid = threadIdx.x;
    if (blockIdx.x == 0 && tid < 256) g_tilestat[tid] = 0ull;
    int i = blockIdx.x * blockDim.x + tid;
    if (i >= E) return;
    int d = is64 ? (int)((const long long*)edges)[(size_t)E + i]
                 : ((const int*)edges)[(size_t)E + i];
    atomicAdd(&g_counts[d], 1);
}

// ---------------------------------------------------------------------------
// 2. single-pass decoupled-lookback scan + self-loop + cursor init.
//    Tile = 512 counts. Status word: flag(2b)<<62 | value.
//    flag 1 = aggregate ready, 2 = inclusive prefix ready.
// ---------------------------------------------------------------------------
__global__ __launch_bounds__(SCAN_T) void scan_lookback_kernel(int N) {
    __shared__ int warp_sums[16];
    __shared__ int s_base;
    int t = threadIdx.x;
    int b = blockIdx.x;
    int lane = t & 31;
    int wid = t >> 5;
    int i = b * SCAN_T + t;

    int v = 0;
    if (i < N) { v = g_counts[i] + 1; g_counts[i] = 0; }

    // warp inclusive scan
    int incl = v;
    #pragma unroll
    for (int o = 1; o < 32; o <<= 1) {
        int n = __shfl_up_sync(0xffffffffu, incl, o);
        if (lane >= o) incl += n;
    }
    if (lane == 31) warp_sums[wid] = incl;
    __syncthreads();
    if (wid == 0) {
        int ws = (lane < 16) ? warp_sums[lane] : 0;
        #pragma unroll
        for (int o = 1; o < 16; o <<= 1) {
            int n = __shfl_up_sync(0xffffffffu, ws, o);
            if (lane >= o) ws += n;
        }
        if (lane < 16) warp_sums[lane] = ws;
    }
    __syncthreads();
    int block_excl = (wid > 0 ? warp_sums[wid - 1] : 0) + incl - v;
    int total = warp_sums[15];

    if (t == 0) {
        int base = 0;
        if (b == 0) {
            atomicExch(&g_tilestat[0], (2ull << 62) | (unsigned long long)total);
        } else {
            atomicExch(&g_tilestat[b], (1ull << 62) | (unsigned long long)total);
            int j = b - 1;
            while (true) {
                unsigned long long s = atomicAdd(&g_tilestat[j], 0ull);
                unsigned f = (unsigned)(s >> 62);
                if (f == 2u) { base += (int)(s & 0x3FFFFFFFFFFFFFFFull); break; }
                if (f == 1u) { base += (int)(s & 0x3FFFFFFFFFFFFFFFull); j--; }
            }
            atomicExch(&g_tilestat[b], (2ull << 62) | (unsigned long long)(base + total));
        }
        s_base = base;
    }
    __syncthreads();

    int o = s_base + block_excl;
    if (i < N) {
        g_offsets[i] = o;
        g_csr[o] = i;           // self-loop first in segment
        g_cursor[i] = o + 1;
        if (i == N - 1) g_offsets[N] = o + v;
    }
}

// ---------------------------------------------------------------------------
// 3. scatter (+ inline detection)
// ---------------------------------------------------------------------------
__global__ void scatter_kernel(const void* __restrict__ edges, int E) {
    bool is64 = detect_is64_block(edges, E);
    int i = blockIdx.x * blockDim.x + threadIdx.x;
    if (i >= E) return;
    int s, d;
    if (is64) {
        s = (int)((const long long*)edges)[i];
        d = (int)((const long long*)edges)[(size_t)E + i];
    } else {
        s = ((const int*)edges)[i];
        d = ((const int*)edges)[(size_t)E + i];
    }
    g_csr[atomicAdd(&g_cursor[d], 1)] = s;
}

// ---------------------------------------------------------------------------
// 4. tensor-core GEMM: 128x128 block, K=128 fully resident in smem.
// ---------------------------------------------------------------------------
extern __shared__ __half smem_dyn[];

__global__ __launch_bounds__(256) void gemm_kernel(
    const float* __restrict__ x, const float* __restrict__ W,
    const float* __restrict__ att_s, const float* __restrict__ att_d, int N)
{
    __half* Asm  = smem_dyn;                    // x tile (later: h staging)
    __half* WTsm = smem_dyn + 128 * ASTRIDE;    // W transposed
    __shared__ unsigned s_amax;

    int tid = threadIdx.x;
    int lane = tid & 31;
    int wid = tid >> 5;
    int warp_m = wid & 3;
    int warp_n = wid >> 2;
    int m_base = warp_m * 32;
    int n_base = warp_n * 64;
    int rowBase = blockIdx.x * 128;
    if (tid == 0) s_amax = enc_f(-3.402823466e38f);

    const float4* x4 = (const float4*)x;
    const float4* W4 = (const float4*)W;

    #pragma unroll
    for (int i = 0; i < 16; i++) {
        int idx = tid + i * 256;
        int r = idx >> 5;
        int c4 = idx & 31;
        int gr = rowBase + r;
        float4 v = make_float4(0.f, 0.f, 0.f, 0.f);
        if (gr < N) v = x4[(size_t)gr * 32 + c4];
        __half2* p = (__half2*)(Asm + r * ASTRIDE + c4 * 4);
        p[0] = __floats2half2_rn(v.x, v.y);
        p[1] = __floats2half2_rn(v.z, v.w);
    }
    #pragma unroll
    for (int i = 0; i < 16; i++) {
        int idx = tid + i * 256;
        int k = idx >> 5;
        int n4 = idx & 31;
        float4 v = W4[k * 32 + n4];
        WTsm[(n4 * 4 + 0) * ASTRIDE + k] = __float2half_rn(v.x);
        WTsm[(n4 * 4 + 1) * ASTRIDE + k] = __float2half_rn(v.y);
        WTsm[(n4 * 4 + 2) * ASTRIDE + k] = __float2half_rn(v.z);
        WTsm[(n4 * 4 + 3) * ASTRIDE + k] = __float2half_rn(v.w);
    }
    __syncthreads();

    float d[2][8][4];
    #pragma unroll
    for (int mi = 0; mi < 2; mi++)
        #pragma unroll
        for (int ni = 0; ni < 8; ni++)
            #pragma unroll
            for (int j = 0; j < 4; j++) d[mi][ni][j] = 0.f;

    uint32_t a_base = smem_u32(Asm);
    uint32_t w_base = smem_u32(WTsm);

    #pragma unroll
    for (int ks = 0; ks < 8; ks++) {
        int k = ks * 16;
        uint32_t a[2][4];
        #pragma unroll
        for (int mi = 0; mi < 2; mi++) {
            int row = m_base + mi * 16 + (lane & 15);
            uint32_t addr = a_base + (uint32_t)(row * ASTRIDE + k) * 2 + ((lane >> 4) << 4);
            ldsm_x4(a[mi], addr);
        }
        uint32_t b[4][4];
        #pragma unroll
        for (int nj = 0; nj < 4; nj++) {
            int quad = lane >> 3;
            int nrow = n_base + nj * 16 + ((quad >> 1) << 3) + (lane & 7);
            int kcol = k + ((quad & 1) << 3);
            uint32_t addr = w_base + (uint32_t)(nrow * ASTRIDE + kcol) * 2;
            ldsm_x4(b[nj], addr);
        }
        #pragma unroll
        for (int mi = 0; mi < 2; mi++)
            #pragma unroll
            for (int nj = 0; nj < 4; nj++) {
                mma16816(d[mi][2 * nj],     a[mi], b[nj][0], b[nj][1]);
                mma16816(d[mi][2 * nj + 1], a[mi], b[nj][2], b[nj][3]);
            }
    }
    __syncthreads();   // all A reads done before staging h into Asm

    {
        int g = lane >> 2;
        int tg = lane & 3;
        #pragma unroll
        for (int mi = 0; mi < 2; mi++)
            #pragma unroll
            for (int ni = 0; ni < 8; ni++) {
                int row = m_base + mi * 16 + g;
                int col = n_base + ni * 8 + tg * 2;
                *(__half2*)(Asm + row * ASTRIDE + col) =
                    __floats2half2_rn(d[mi][ni][0], d[mi][ni][1]);
                *(__half2*)(Asm + (row + 8) * ASTRIDE + col) =
                    __floats2half2_rn(d[mi][ni][2], d[mi][ni][3]);
            }
    }
    __syncthreads();

    int tx = tid & 15;
    int ty = tid >> 4;
    float s_c[8], d_c[8];
    *(float4*)&s_c[0] = ((const float4*)att_s)[tx * 2];
    *(float4*)&s_c[4] = ((const float4*)att_s)[tx * 2 + 1];
    *(float4*)&d_c[0] = ((const float4*)att_d)[tx * 2];
    *(float4*)&d_c[4] = ((const float4*)att_d)[tx * 2 + 1];

    float lmax = -3.402823466e38f;
    #pragma unroll
    for (int rr = 0; rr < 8; rr++) {
        int r = ty * 8 + rr;
        int gr = rowBase + r;
        uint4 pkt = *(uint4*)(Asm + r * ASTRIDE + tx * 8);
        float2 f0 = __half22float2(u32_as_h2(pkt.x));
        float2 f1 = __half22float2(u32_as_h2(pkt.y));
        float2 f2 = __half22float2(u32_as_h2(pkt.z));
        float2 f3 = __half22float2(u32_as_h2(pkt.w));
        float ps = f0.x * s_c[0] + f0.y * s_c[1] + f1.x * s_c[2] + f1.y * s_c[3]
                 + f2.x * s_c[4] + f2.y * s_c[5] + f3.x * s_c[6] + f3.y * s_c[7];
        float pd = f0.x * d_c[0] + f0.y * d_c[1] + f1.x * d_c[2] + f1.y * d_c[3]
                 + f2.x * d_c[4] + f2.y * d_c[5] + f3.x * d_c[6] + f3.y * d_c[7];
        #pragma unroll
        for (int o = 8; o > 0; o >>= 1) {
            ps += __shfl_xor_sync(0xffffffffu, ps, o);
            pd += __shfl_xor_sync(0xffffffffu, pd, o);
        }
        if (gr < N) {
            if (tx == 0) { g_asrc[gr] = ps; g_adst[gr] = pd; lmax = fmaxf(lmax, ps); }
            ((uint4*)g_h16)[(size_t)gr * 16 + tx] = pkt;
        }
    }
    if (tx == 0) atomicMax(&s_amax, enc_f(lmax));
    __syncthreads();
    if (tid == 0) atomicMax(&g_amax, s_amax);
}

// ---------------------------------------------------------------------------
// 5. single-pass aggregation: 2 nodes per warp, 16 lanes per node.
// ---------------------------------------------------------------------------
__global__ __launch_bounds__(256) void aggregate_kernel(
    const float* __restrict__ bias, float* __restrict__ out, int N)
{
    int warp = (blockIdx.x * blockDim.x + threadIdx.x) >> 5;
    int lane = threadIdx.x & 31;
    int half = lane >> 4;
    int sub  = lane & 15;
    int node = warp * 2 + half;
    bool valid = node < N;
    int nodeC = valid ? node : 0;

    int beg = g_offsets[nodeC];
    int end = g_offsets[nodeC + 1];
    float adst = g_adst[nodeC];
    float gmax = dec_f(g_amax);
    float t = gmax + adst;
    float mb = fmaxf(t, 0.2f * t);

    int deg = end - beg;
    int degmax = __reduce_max_sync(0xffffffffu, deg);

    float acc[8];
    #pragma unroll
    for (int i = 0; i < 8; i++) acc[i] = 0.f;
    float ssum = 0.f;
    const uint4* h4 = (const uint4*)g_h16;
    int last = end - 1;

    for (int i = 0; i < degmax; i += 4) {
        int k0 = beg + i;
        int k1 = k0 + 1, k2 = k0 + 2, k3 = k0 + 3;
        int c0 = min(k0, last), c1 = min(k1, last);
        int c2 = min(k2, last), c3 = min(k3, last);
        int s0 = g_csr[c0];
        int s1 = g_csr[c1];
        int s2 = g_csr[c2];
        int s3 = g_csr[c3];
        float e0 = g_asrc[s0] + adst;
        float e1 = g_asrc[s1] + adst;
        float e2 = g_asrc[s2] + adst;
        float e3 = g_asrc[s3] + adst;
        uint4 v0 = h4[(size_t)s0 * 16 + sub];
        uint4 v1 = h4[(size_t)s1 * 16 + sub];
        uint4 v2 = h4[(size_t)s2 * 16 + sub];
        uint4 v3 = h4[(size_t)s3 * 16 + sub];
        e0 = fmaxf(e0, 0.2f * e0);
        e1 = fmaxf(e1, 0.2f * e1);
        e2 = fmaxf(e2, 0.2f * e2);
        e3 = fmaxf(e3, 0.2f * e3);
        float w0 = (k0 < end) ? __expf(e0 - mb) : 0.f;
        float w1 = (k1 < end) ? __expf(e1 - mb) : 0.f;
        float w2 = (k2 < end) ? __expf(e2 - mb) : 0.f;
        float w3 = (k3 < end) ? __expf(e3 - mb) : 0.f;
        ssum += (w0 + w1) + (w2 + w3);
        #pragma unroll
        for (int j = 0; j < 4; j++) {
            unsigned p0 = (&v0.x)[j], p1 = (&v1.x)[j], p2 = (&v2.x)[j], p3 = (&v3.x)[j];
            float2 f0 = __half22float2(u32_as_h2(p0));
            float2 f1 = __half22float2(u32_as_h2(p1));
            float2 f2 = __half22float2(u32_as_h2(p2));
            float2 f3 = __half22float2(u32_as_h2(p3));
            acc[j * 2 + 0] += w0 * f0.x + w1 * f1.x + w2 * f2.x + w3 * f3.x;
            acc[j * 2 + 1] += w0 * f0.y + w1 * f1.y + w2 * f2.y + w3 * f3.y;
        }
    }

    if (valid) {
        float inv = 1.0f / (ssum + 1e-16f);
        float4 ba = ((const float4*)bias)[sub * 2];
        float4 bb = ((const float4*)bias)[sub * 2 + 1];
        float4 oa, ob;
        oa.x = fmaxf(acc[0] * inv + ba.x, 0.f);
        oa.y = fmaxf(acc[1] * inv + ba.y, 0.f);
        oa.z = fmaxf(acc[2] * inv + ba.z, 0.f);
        oa.w = fmaxf(acc[3] * inv + ba.w, 0.f);
        ob.x = fmaxf(acc[4] * inv + bb.x, 0.f);
        ob.y = fmaxf(acc[5] * inv + bb.y, 0.f);
        ob.z = fmaxf(acc[6] * inv + bb.z, 0.f);
        ob.w = fmaxf(acc[7] * inv + bb.w, 0.f);
        ((float4*)out)[(size_t)node * 32 + sub * 2]     = oa;
        ((float4*)out)[(size_t)node * 32 + sub * 2 + 1] = ob;
    }
}

// ---------------------------------------------------------------------------
// launch: fork GEMM onto a side stream, overlap with 3-kernel CSR build,
// join before aggregate.
// ---------------------------------------------------------------------------
extern "C" void kernel_launch(void* const* d_in, const int* in_sizes, int n_in,
                              void* d_out, int out_size) {
    const float* x     = (const float*)d_in[0];
    const void*  edges = d_in[1];
    const float* W     = (const float*)d_in[2];
    const float* att_s = (const float*)d_in[3];
    const float* att_d = (const float*)d_in[4];
    const float* bias  = (const float*)d_in[5];
    float* out = (float*)d_out;

    int N = in_sizes[0] / 128;
    int E = in_sizes[1] / 2;
    if (N > MAXN) N = MAXN;
    if (E > MAXE) E = MAXE;

    int nbE  = (E + 255) / 256;
    int nbSc = (N + SCAN_T - 1) / SCAN_T;

    cudaStream_t s2;
    cudaStreamCreate(&s2);
    cudaEvent_t evFork, evJoin;
    cudaEventCreateWithFlags(&evFork, cudaEventDisableTiming);
    cudaEventCreateWithFlags(&evJoin, cudaEventDisableTiming);

    // ---- fork: GEMM on side stream (independent of edge data) ----
    cudaEventRecord(evFork, 0);
    cudaStreamWaitEvent(s2, evFork, 0);
    int smem_bytes = 2 * 128 * ASTRIDE * sizeof(__half);   // 69,632 B
    cudaFuncSetAttribute(gemm_kernel,
                         cudaFuncAttributeMaxDynamicSharedMemorySize, smem_bytes);
    gemm_kernel<<<(N + 127) / 128, 256, smem_bytes, s2>>>(x, W, att_s, att_d, N);

    // ---- CSR build chain (3 kernels) on the main stream ----
    count_edges_kernel<<<nbE, 256>>>(edges, E);
    scan_lookback_kernel<<<nbSc, SCAN_T>>>(N);
    scatter_kernel<<<nbE, 256>>>(edges, E);

    // ---- join: aggregate needs both GEMM outputs and the CSR ----
    cudaEventRecord(evJoin, s2);
    cudaStreamWaitEvent(0, evJoin, 0);
    aggregate_kernel<<<(N + 15) / 16, 256>>>(bias, out, N);
}

// round 15
// speedup vs baseline: 1.0004x; 1.0004x over previous
#include <cuda_runtime.h>
#include <cuda_fp16.h>
#include <cstdint>

// ---------------------------------------------------------------------------
// GAT layer. Graph-parallel pipeline:
//   NULL stream:  count(+detect,+rank/dst persist) -> lookback-scan(+selfloop)
//                 -> scatter (atomic-free, rank-based)                 ┐
//   side stream:  GEMM h=xW (HMMA tensor cores)                       ├→ aggregate
// ---------------------------------------------------------------------------

#define MAXN 100000
#define MAXE 1600000
#define SCAN_T 512
#define ASTRIDE 136   // 128 halfs + 8 pad -> 272B row stride (4-bank shift/row)

__device__ __half g_h16[(size_t)MAXN * 128];
__device__ float g_asrc[MAXN];
__device__ float g_adst[MAXN];
__device__ int   g_counts[MAXN];
__device__ int   g_offsets[MAXN + 1];
__device__ int   g_csr[MAXN + MAXE];
__device__ int   g_rank[MAXE];    // edge's rank within its dst segment (from count's atomicAdd)
__device__ int   g_dst32[MAXE];   // decoded dst ids (skip int64 reload in scatter)
__device__ unsigned long long g_tilestat[256];   // lookback status; re-zeroed by count each call
__device__ unsigned g_amax = 0x00800000u;        // enc_f(-FLT_MAX); monotone, replay-idempotent

__device__ __forceinline__ unsigned h2_as_u32(__half2 h) {
    union { __half2 h; unsigned u; } c; c.h = h; return c.u;
}
__device__ __forceinline__ __half2 u32_as_h2(unsigned u) {
    union { unsigned u; __half2 h; } c; c.u = u; return c.h;
}
__device__ __forceinline__ unsigned enc_f(float f) {
    unsigned u = __float_as_uint(f);
    return (u & 0x80000000u) ? ~u : (u | 0x80000000u);
}
__device__ __forceinline__ float dec_f(unsigned e) {
    return (e & 0x80000000u) ? __uint_as_float(e ^ 0x80000000u)
                             : __uint_as_float(~e);
}
__device__ __forceinline__ uint32_t smem_u32(const void* p) {
    return (uint32_t)__cvta_generic_to_shared(p);
}
__device__ __forceinline__ void ldsm_x4(uint32_t* r, uint32_t addr) {
    asm volatile("ldmatrix.sync.aligned.m8n8.x4.shared.b16 {%0,%1,%2,%3}, [%4];"
                 : "=r"(r[0]), "=r"(r[1]), "=r"(r[2]), "=r"(r[3]) : "r"(addr));
}
__device__ __forceinline__ void mma16816(float* d, const uint32_t* a,
                                         uint32_t b0, uint32_t b1) {
    asm volatile(
        "mma.sync.aligned.m16n8k16.row.col.f32.f16.f16.f32 "
        "{%0,%1,%2,%3}, {%4,%5,%6,%7}, {%8,%9}, {%0,%1,%2,%3};"
        : "+f"(d[0]), "+f"(d[1]), "+f"(d[2]), "+f"(d[3])
        : "r"(a[0]), "r"(a[1]), "r"(a[2]), "r"(a[3]), "r"(b0), "r"(b1));
}

// inline per-block dtype detection: sample first 256 odd 32-bit words.
// int64 => high halves, all zero. int32 => src node ids (P(all 0) ~ 0).
__device__ __forceinline__ bool detect_is64_block(const void* edges, int E) {
    const unsigned* w = (const unsigned*)edges;
    int samp = threadIdx.x & 255;
    int nz = (samp < E) ? (w[2 * (size_t)samp + 1] != 0u) : 0;
    return __syncthreads_or(nz) == 0;
}

// ---------------------------------------------------------------------------
// 1. histogram + rank/dst persist (+ tilestat zeroing + inline detection)
// ---------------------------------------------------------------------------
__global__ void count_edges_kernel(const void* __restrict__ edges, int E) {
    bool is64 = detect_is64_block(edges, E);
    int tid = threadIdx.x;
    if (blockIdx.x == 0 && tid < 256) g_tilestat[tid] = 0ull;
    int i = blockIdx.x * blockDim.x + tid;
    if (i >= E) return;
    int d = is64 ? (int)((const long long*)edges)[(size_t)E + i]
                 : ((const int*)edges)[(size_t)E + i];
    g_dst32[i] = d;
    g_rank[i] = atomicAdd(&g_counts[d], 1);
}

// ---------------------------------------------------------------------------
// 2. single-pass decoupled-lookback scan + self-loop + cursor-free offsets.
// ---------------------------------------------------------------------------
__global__ __launch_bounds__(SCAN_T) void scan_lookback_kernel(int N) {
    __shared__ int warp_sums[16];
    __shared__ int s_base;
    int t = threadIdx.x;
    int b = blockIdx.x;
    int lane = t & 31;
    int wid = t >> 5;
    int i = b * SCAN_T + t;

    int v = 0;
    if (i < N) { v = g_counts[i] + 1; g_counts[i] = 0; }

    int incl = v;
    #pragma unroll
    for (int o = 1; o < 32; o <<= 1) {
        int n = __shfl_up_sync(0xffffffffu, incl, o);
        if (lane >= o) incl += n;
    }
    if (lane == 31) warp_sums[wid] = incl;
    __syncthreads();
    if (wid == 0) {
        int ws = (lane < 16) ? warp_sums[lane] : 0;
        #pragma unroll
        for (int o = 1; o < 16; o <<= 1) {
            int n = __shfl_up_sync(0xffffffffu, ws, o);
            if (lane >= o) ws += n;
        }
        if (lane < 16) warp_sums[lane] = ws;
    }
    __syncthreads();
    int block_excl = (wid > 0 ? warp_sums[wid - 1] : 0) + incl - v;
    int total = warp_sums[15];

    if (t == 0) {
        int base = 0;
        if (b == 0) {
            atomicExch(&g_tilestat[0], (2ull << 62) | (unsigned long long)total);
        } else {
            atomicExch(&g_tilestat[b], (1ull << 62) | (unsigned long long)total);
            int j = b - 1;
            while (true) {
                unsigned long long s = atomicAdd(&g_tilestat[j], 0ull);
                unsigned f = (unsigned)(s >> 62);
                if (f == 2u) { base += (int)(s & 0x3FFFFFFFFFFFFFFFull); break; }
                if (f == 1u) { base += (int)(s & 0x3FFFFFFFFFFFFFFFull); j--; }
            }
            atomicExch(&g_tilestat[b], (2ull << 62) | (unsigned long long)(base + total));
        }
        s_base = base;
    }
    __syncthreads();

    int o = s_base + block_excl;
    if (i < N) {
        g_offsets[i] = o;
        g_csr[o] = i;           // self-loop first in segment
        if (i == N - 1) g_offsets[N] = o + v;
    }
}

// ---------------------------------------------------------------------------
// 3. scatter, atomic-free: pos = offsets[d] + 1 + rank (positions are a
//    permutation of each segment; order nondeterminism same as atomic version)
// ---------------------------------------------------------------------------
__global__ void scatter_kernel(const void* __restrict__ edges, int E) {
    bool is64 = detect_is64_block(edges, E);
    int i = blockIdx.x * blockDim.x + threadIdx.x;
    if (i >= E) return;
    int s = is64 ? (int)((const long long*)edges)[i] : ((const int*)edges)[i];
    int d = g_dst32[i];
    g_csr[g_offsets[d] + 1 + g_rank[i]] = s;
}

// ---------------------------------------------------------------------------
// 4. tensor-core GEMM: 128x128 block, K=128 fully resident in smem.
// ---------------------------------------------------------------------------
extern __shared__ __half smem_dyn[];

__global__ __launch_bounds__(256) void gemm_kernel(
    const float* __restrict__ x, const float* __restrict__ W,
    const float* __restrict__ att_s, const float* __restrict__ att_d, int N)
{
    __half* Asm  = smem_dyn;                    // x tile (later: h staging)
    __half* WTsm = smem_dyn + 128 * ASTRIDE;    // W transposed
    __shared__ unsigned s_amax;

    int tid = threadIdx.x;
    int lane = tid & 31;
    int wid = tid >> 5;
    int warp_m = wid & 3;
    int warp_n = wid >> 2;
    int m_base = warp_m * 32;
    int n_base = warp_n * 64;
    int rowBase = blockIdx.x * 128;
    if (tid == 0) s_amax = enc_f(-3.402823466e38f);

    const float4* x4 = (const float4*)x;
    const float4* W4 = (const float4*)W;

    #pragma unroll
    for (int i = 0; i < 16; i++) {
        int idx = tid + i * 256;
        int r = idx >> 5;
        int c4 = idx & 31;
        int gr = rowBase + r;
        float4 v = make_float4(0.f, 0.f, 0.f, 0.f);
        if (gr < N) v = x4[(size_t)gr * 32 + c4];
        __half2* p = (__half2*)(Asm + r * ASTRIDE + c4 * 4);
        p[0] = __floats2half2_rn(v.x, v.y);
        p[1] = __floats2half2_rn(v.z, v.w);
    }
    #pragma unroll
    for (int i = 0; i < 16; i++) {
        int idx = tid + i * 256;
        int k = idx >> 5;
        int n4 = idx & 31;
        float4 v = W4[k * 32 + n4];
        WTsm[(n4 * 4 + 0) * ASTRIDE + k] = __float2half_rn(v.x);
        WTsm[(n4 * 4 + 1) * ASTRIDE + k] = __float2half_rn(v.y);
        WTsm[(n4 * 4 + 2) * ASTRIDE + k] = __float2half_rn(v.z);
        WTsm[(n4 * 4 + 3) * ASTRIDE + k] = __float2half_rn(v.w);
    }
    __syncthreads();

    float d[2][8][4];
    #pragma unroll
    for (int mi = 0; mi < 2; mi++)
        #pragma unroll
        for (int ni = 0; ni < 8; ni++)
            #pragma unroll
            for (int j = 0; j < 4; j++) d[mi][ni][j] = 0.f;

    uint32_t a_base = smem_u32(Asm);
    uint32_t w_base = smem_u32(WTsm);

    #pragma unroll
    for (int ks = 0; ks < 8; ks++) {
        int k = ks * 16;
        uint32_t a[2][4];
        #pragma unroll
        for (int mi = 0; mi < 2; mi++) {
            int row = m_base + mi * 16 + (lane & 15);
            uint32_t addr = a_base + (uint32_t)(row * ASTRIDE + k) * 2 + ((lane >> 4) << 4);
            ldsm_x4(a[mi], addr);
        }
        uint32_t b[4][4];
        #pragma unroll
        for (int nj = 0; nj < 4; nj++) {
            int quad = lane >> 3;
            int nrow = n_base + nj * 16 + ((quad >> 1) << 3) + (lane & 7);
            int kcol = k + ((quad & 1) << 3);
            uint32_t addr = w_base + (uint32_t)(nrow * ASTRIDE + kcol) * 2;
            ldsm_x4(b[nj], addr);
        }
        #pragma unroll
        for (int mi = 0; mi < 2; mi++)
            #pragma unroll
            for (int nj = 0; nj < 4; nj++) {
                mma16816(d[mi][2 * nj],     a[mi], b[nj][0], b[nj][1]);
                mma16816(d[mi][2 * nj + 1], a[mi], b[nj][2], b[nj][3]);
            }
    }
    __syncthreads();   // all A reads done before staging h into Asm

    {
        int g = lane >> 2;
        int tg = lane & 3;
        #pragma unroll
        for (int mi = 0; mi < 2; mi++)
            #pragma unroll
            for (int ni = 0; ni < 8; ni++) {
                int row = m_base + mi * 16 + g;
                int col = n_base + ni * 8 + tg * 2;
                *(__half2*)(Asm + row * ASTRIDE + col) =
                    __floats2half2_rn(d[mi][ni][0], d[mi][ni][1]);
                *(__half2*)(Asm + (row + 8) * ASTRIDE + col) =
                    __floats2half2_rn(d[mi][ni][2], d[mi][ni][3]);
            }
    }
    __syncthreads();

    int tx = tid & 15;
    int ty = tid >> 4;
    float s_c[8], d_c[8];
    *(float4*)&s_c[0] = ((const float4*)att_s)[tx * 2];
    *(float4*)&s_c[4] = ((const float4*)att_s)[tx * 2 + 1];
    *(float4*)&d_c[0] = ((const float4*)att_d)[tx * 2];
    *(float4*)&d_c[4] = ((const float4*)att_d)[tx * 2 + 1];

    float lmax = -3.402823466e38f;
    #pragma unroll
    for (int rr = 0; rr < 8; rr++) {
        int r = ty * 8 + rr;
        int gr = rowBase + r;
        uint4 pkt = *(uint4*)(Asm + r * ASTRIDE + tx * 8);
        float2 f0 = __half22float2(u32_as_h2(pkt.x));
        float2 f1 = __half22float2(u32_as_h2(pkt.y));
        float2 f2 = __half22float2(u32_as_h2(pkt.z));
        float2 f3 = __half22float2(u32_as_h2(pkt.w));
        float ps = f0.x * s_c[0] + f0.y * s_c[1] + f1.x * s_c[2] + f1.y * s_c[3]
                 + f2.x * s_c[4] + f2.y * s_c[5] + f3.x * s_c[6] + f3.y * s_c[7];
        float pd = f0.x * d_c[0] + f0.y * d_c[1] + f1.x * d_c[2] + f1.y * d_c[3]
                 + f2.x * d_c[4] + f2.y * d_c[5] + f3.x * d_c[6] + f3.y * d_c[7];
        #pragma unroll
        for (int o = 8; o > 0; o >>= 1) {
            ps += __shfl_xor_sync(0xffffffffu, ps, o);
            pd += __shfl_xor_sync(0xffffffffu, pd, o);
        }
        if (gr < N) {
            if (tx == 0) { g_asrc[gr] = ps; g_adst[gr] = pd; lmax = fmaxf(lmax, ps); }
            ((uint4*)g_h16)[(size_t)gr * 16 + tx] = pkt;
        }
    }
    if (tx == 0) atomicMax(&s_amax, enc_f(lmax));
    __syncthreads();
    if (tid == 0) atomicMax(&g_amax, s_amax);
}

// ---------------------------------------------------------------------------
// 5. single-pass aggregation: 2 nodes per warp, 16 lanes per node.
// ---------------------------------------------------------------------------
__global__ __launch_bounds__(256) void aggregate_kernel(
    const float* __restrict__ bias, float* __restrict__ out, int N)
{
    int warp = (blockIdx.x * blockDim.x + threadIdx.x) >> 5;
    int lane = threadIdx.x & 31;
    int half = lane >> 4;
    int sub  = lane & 15;
    int node = warp * 2 + half;
    bool valid = node < N;
    int nodeC = valid ? node : 0;

    int beg = g_offsets[nodeC];
    int end = g_offsets[nodeC + 1];
    float adst = g_adst[nodeC];
    float gmax = dec_f(g_amax);
    float t = gmax + adst;
    float mb = fmaxf(t, 0.2f * t);

    int deg = end - beg;
    int degmax = __reduce_max_sync(0xffffffffu, deg);

    float acc[8];
    #pragma unroll
    for (int i = 0; i < 8; i++) acc[i] = 0.f;
    float ssum = 0.f;
    const uint4* h4 = (const uint4*)g_h16;
    int last = end - 1;

    for (int i = 0; i < degmax; i += 4) {
        int k0 = beg + i;
        int k1 = k0 + 1, k2 = k0 + 2, k3 = k0 + 3;
        int c0 = min(k0, last), c1 = min(k1, last);
        int c2 = min(k2, last), c3 = min(k3, last);
        int s0 = g_csr[c0];
        int s1 = g_csr[c1];
        int s2 = g_csr[c2];
        int s3 = g_csr[c3];
        float e0 = g_asrc[s0] + adst;
        float e1 = g_asrc[s1] + adst;
        float e2 = g_asrc[s2] + adst;
        float e3 = g_asrc[s3] + adst;
        uint4 v0 = h4[(size_t)s0 * 16 + sub];
        uint4 v1 = h4[(size_t)s1 * 16 + sub];
        uint4 v2 = h4[(size_t)s2 * 16 + sub];
        uint4 v3 = h4[(size_t)s3 * 16 + sub];
        e0 = fmaxf(e0, 0.2f * e0);
        e1 = fmaxf(e1, 0.2f * e1);
        e2 = fmaxf(e2, 0.2f * e2);
        e3 = fmaxf(e3, 0.2f * e3);
        float w0 = (k0 < end) ? __expf(e0 - mb) : 0.f;
        float w1 = (k1 < end) ? __expf(e1 - mb) : 0.f;
        float w2 = (k2 < end) ? __expf(e2 - mb) : 0.f;
        float w3 = (k3 < end) ? __expf(e3 - mb) : 0.f;
        ssum += (w0 + w1) + (w2 + w3);
        #pragma unroll
        for (int j = 0; j < 4; j++) {
            unsigned p0 = (&v0.x)[j], p1 = (&v1.x)[j], p2 = (&v2.x)[j], p3 = (&v3.x)[j];
            float2 f0 = __half22float2(u32_as_h2(p0));
            float2 f1 = __half22float2(u32_as_h2(p1));
            float2 f2 = __half22float2(u32_as_h2(p2));
            float2 f3 = __half22float2(u32_as_h2(p3));
            acc[j * 2 + 0] += w0 * f0.x + w1 * f1.x + w2 * f2.x + w3 * f3.x;
            acc[j * 2 + 1] += w0 * f0.y + w1 * f1.y + w2 * f2.y + w3 * f3.y;
        }
    }

    if (valid) {
        float inv = 1.0f / (ssum + 1e-16f);
        float4 ba = ((const float4*)bias)[sub * 2];
        float4 bb = ((const float4*)bias)[sub * 2 + 1];
        float4 oa, ob;
        oa.x = fmaxf(acc[0] * inv + ba.x, 0.f);
        oa.y = fmaxf(acc[1] * inv + ba.y, 0.f);
        oa.z = fmaxf(acc[2] * inv + ba.z, 0.f);
        oa.w = fmaxf(acc[3] * inv + ba.w, 0.f);
        ob.x = fmaxf(acc[4] * inv + bb.x, 0.f);
        ob.y = fmaxf(acc[5] * inv + bb.y, 0.f);
        ob.z = fmaxf(acc[6] * inv + bb.z, 0.f);
        ob.w = fmaxf(acc[7] * inv + bb.w, 0.f);
        ((float4*)out)[(size_t)node * 32 + sub * 2]     = oa;
        ((float4*)out)[(size_t)node * 32 + sub * 2 + 1] = ob;
    }
}

// ---------------------------------------------------------------------------
// launch: fork GEMM onto a side stream, overlap with 3-kernel CSR build,
// join before aggregate.
// ---------------------------------------------------------------------------
extern "C" void kernel_launch(void* const* d_in, const int* in_sizes, int n_in,
                              void* d_out, int out_size) {
    const float* x     = (const float*)d_in[0];
    const void*  edges = d_in[1];
    const float* W     = (const float*)d_in[2];
    const float* att_s = (const float*)d_in[3];
    const float* att_d = (const float*)d_in[4];
    const float* bias  = (const float*)d_in[5];
    float* out = (float*)d_out;

    int N = in_sizes[0] / 128;
    int E = in_sizes[1] / 2;
    if (N > MAXN) N = MAXN;
    if (E > MAXE) E = MAXE;

    int nbE  = (E + 255) / 256;
    int nbSc = (N + SCAN_T - 1) / SCAN_T;

    cudaStream_t s2;
    cudaStreamCreate(&s2);
    cudaEvent_t evFork, evJoin;
    cudaEventCreateWithFlags(&evFork, cudaEventDisableTiming);
    cudaEventCreateWithFlags(&evJoin, cudaEventDisableTiming);

    // ---- fork: GEMM on side stream (independent of edge data) ----
    cudaEventRecord(evFork, 0);
    cudaStreamWaitEvent(s2, evFork, 0);
    int smem_bytes = 2 * 128 * ASTRIDE * sizeof(__half);   // 69,632 B
    cudaFuncSetAttribute(gemm_kernel,
                         cudaFuncAttributeMaxDynamicSharedMemorySize, smem_bytes);
    gemm_kernel<<<(N + 127) / 128, 256, smem_bytes, s2>>>(x, W, att_s, att_d, N);

    // ---- CSR build chain (3 kernels) on the main stream ----
    count_edges_kernel<<<nbE, 256>>>(edges, E);
    scan_lookback_kernel<<<nbSc, SCAN_T>>>(N);
    scatter_kernel<<<nbE, 256>>>(edges, E);

    // ---- join: aggregate needs both GEMM outputs and the CSR ----
    cudaEventRecord(evJoin, s2);
    cudaStreamWaitEvent(0, evJoin, 0);
    aggregate_kernel<<<(N + 15) / 16, 256>>>(bias, out, N);
}